// round 5
// baseline (speedup 1.0000x reference)
#include <cuda_runtime.h>
#include <cuda_bf16.h>
#include <math.h>

#define NN 50000
#define DIN 128
#define HH 256
#define DOUT 256

// ---- scratch (device globals; no allocation allowed) ----
__device__ float g_h[NN * HH];     // current activations
__device__ float g_hW[NN * HH];    // h @ W scratch
__device__ float g_agg[NN * HH];   // aggregation scratch / logits
__device__ float g_deg[NN];
__device__ float g_dinv[NN];

// ============================================================
// SGEMM: C[M,Nc] = A[M,K] @ B[K,Nc] (+bias)(relu)
// BM=128 BN=128 BK=16, 256 threads, 8x8 per-thread tile
// ============================================================
template <bool BIAS, bool RELU>
__global__ __launch_bounds__(256) void sgemm_kernel(
    const float* __restrict__ A, const float* __restrict__ B,
    const float* __restrict__ bias, float* __restrict__ C,
    int M, int K, int Nc)
{
    const int BM = 128, BN = 128, BK = 16;
    __shared__ float As[BK][BM + 4];
    __shared__ float Bs[BK][BN];

    int tid = threadIdx.x;
    int tx = tid & 15;          // 0..15 -> col group
    int ty = tid >> 4;          // 0..15 -> row group
    int rowBase = blockIdx.x * BM;
    int colBase = blockIdx.y * BN;

    float acc[8][8];
#pragma unroll
    for (int i = 0; i < 8; i++)
#pragma unroll
        for (int j = 0; j < 8; j++) acc[i][j] = 0.0f;

    int nK = K / BK;
    for (int t = 0; t < nK; t++) {
        int kBase = t * BK;
        // load A tile (BM x BK) -> transposed into As[BK][BM]
#pragma unroll
        for (int it = 0; it < 2; it++) {
            int idx = tid + it * 256;       // 0..511 float4s
            int r = idx >> 2;               // 0..127
            int c4 = idx & 3;               // 0..3
            int grow = rowBase + r;
            float4 v = make_float4(0.f, 0.f, 0.f, 0.f);
            if (grow < M)
                v = *(const float4*)&A[(size_t)grow * K + kBase + c4 * 4];
            As[c4 * 4 + 0][r] = v.x;
            As[c4 * 4 + 1][r] = v.y;
            As[c4 * 4 + 2][r] = v.z;
            As[c4 * 4 + 3][r] = v.w;
        }
        // load B tile (BK x BN)
#pragma unroll
        for (int it = 0; it < 2; it++) {
            int idx = tid + it * 256;
            int r = idx >> 5;               // 0..15
            int c4 = idx & 31;              // 0..31
            float4 v = *(const float4*)&B[(size_t)(kBase + r) * Nc + colBase + c4 * 4];
            *(float4*)&Bs[r][c4 * 4] = v;
        }
        __syncthreads();

#pragma unroll
        for (int kk = 0; kk < BK; kk++) {
            float4 a0 = *(const float4*)&As[kk][ty * 8];
            float4 a1 = *(const float4*)&As[kk][ty * 8 + 4];
            float4 b0 = *(const float4*)&Bs[kk][tx * 8];
            float4 b1 = *(const float4*)&Bs[kk][tx * 8 + 4];
            float a[8] = {a0.x, a0.y, a0.z, a0.w, a1.x, a1.y, a1.z, a1.w};
            float b[8] = {b0.x, b0.y, b0.z, b0.w, b1.x, b1.y, b1.z, b1.w};
#pragma unroll
            for (int i = 0; i < 8; i++)
#pragma unroll
                for (int j = 0; j < 8; j++) acc[i][j] += a[i] * b[j];
        }
        __syncthreads();
    }

    // epilogue
    float bia[8];
    if (BIAS) {
        float4 v0 = *(const float4*)&bias[colBase + tx * 8];
        float4 v1 = *(const float4*)&bias[colBase + tx * 8 + 4];
        bia[0] = v0.x; bia[1] = v0.y; bia[2] = v0.z; bia[3] = v0.w;
        bia[4] = v1.x; bia[5] = v1.y; bia[6] = v1.z; bia[7] = v1.w;
    }
#pragma unroll
    for (int i = 0; i < 8; i++) {
        int grow = rowBase + ty * 8 + i;
        if (grow >= M) continue;
        float out[8];
#pragma unroll
        for (int j = 0; j < 8; j++) {
            float v = acc[i][j];
            if (BIAS) v += bia[j];
            if (RELU) v = fmaxf(v, 0.0f);
            out[j] = v;
        }
        float* cp = &C[(size_t)grow * Nc + colBase + tx * 8];
        *(float4*)&cp[0] = make_float4(out[0], out[1], out[2], out[3]);
        *(float4*)&cp[4] = make_float4(out[4], out[5], out[6], out[7]);
    }
}

// ============================================================
// graph helpers  (edge_index is INT32: src = ei[e], dst = ei[E+e])
// ============================================================
__global__ void zero_deg_kernel() {
    int i = blockIdx.x * blockDim.x + threadIdx.x;
    if (i < NN) g_deg[i] = 0.0f;
}

__global__ void deg_count_kernel(const int* __restrict__ ei, int E) {
    int e = blockIdx.x * blockDim.x + threadIdx.x;
    if (e < E) {
        int d = ei[E + e];
        if ((unsigned)d < (unsigned)NN) atomicAdd(&g_deg[d], 1.0f);
    }
}

__global__ void dinv_kernel() {
    int i = blockIdx.x * blockDim.x + threadIdx.x;
    if (i < NN) g_dinv[i] = rsqrtf(g_deg[i] + 1.0f);
}

// agg = hW * dinv^2 (self-loop term)
__global__ void self_init_kernel(const float* __restrict__ hW, float* __restrict__ agg) {
    int i = blockIdx.x * blockDim.x + threadIdx.x;  // float4 index
    if (i >= NN * (HH / 4)) return;
    int row = i >> 6;  // H/4 = 64
    float d = g_dinv[row];
    float s = d * d;
    float4 v = ((const float4*)hW)[i];
    v.x *= s; v.y *= s; v.z *= s; v.w *= s;
    ((float4*)agg)[i] = v;
}

// one warp per edge: agg[dst] += hW[src] * dinv[src]*dinv[dst]
__global__ void scatter_kernel(const float* __restrict__ hW,
                               const int* __restrict__ ei,
                               float* __restrict__ agg, int E)
{
    int warp = (blockIdx.x * blockDim.x + threadIdx.x) >> 5;
    int lane = threadIdx.x & 31;
    if (warp >= E) return;
    int s = ei[warp];
    int d = ei[E + warp];
    if ((unsigned)s >= (unsigned)NN || (unsigned)d >= (unsigned)NN) return;
    float norm = g_dinv[s] * g_dinv[d];
    const float4* sp = (const float4*)(hW + (size_t)s * HH);
    float* dp = agg + (size_t)d * HH;
#pragma unroll
    for (int it = 0; it < 2; it++) {
        int i = lane + it * 32;           // 0..63 float4s
        float4 v = sp[i];
        atomicAdd(&dp[i * 4 + 0], v.x * norm);
        atomicAdd(&dp[i * 4 + 1], v.y * norm);
        atomicAdd(&dp[i * 4 + 2], v.z * norm);
        atomicAdd(&dp[i * 4 + 3], v.w * norm);
    }
}

// h = relu(agg + bias)
__global__ void bias_relu_kernel(const float* __restrict__ agg,
                                 const float* __restrict__ bias,
                                 float* __restrict__ h)
{
    int i = blockIdx.x * blockDim.x + threadIdx.x;
    if (i >= NN * (HH / 4)) return;
    int c4 = i & 63;
    float4 b = ((const float4*)bias)[c4];
    float4 v = ((const float4*)agg)[i];
    v.x = fmaxf(v.x + b.x, 0.0f);
    v.y = fmaxf(v.y + b.y, 0.0f);
    v.z = fmaxf(v.z + b.z, 0.0f);
    v.w = fmaxf(v.w + b.w, 0.0f);
    ((float4*)h)[i] = v;
}

// softmax per row, one warp per row (256 cols = 2 float4/lane)
__global__ void softmax_kernel(const float* __restrict__ in, float* __restrict__ out) {
    int warp = (blockIdx.x * blockDim.x + threadIdx.x) >> 5;
    int lane = threadIdx.x & 31;
    if (warp >= NN) return;
    const float4* ip = (const float4*)(in + (size_t)warp * DOUT);
    float4 a = ip[lane];
    float4 b = ip[lane + 32];
    float m = fmaxf(fmaxf(fmaxf(a.x, a.y), fmaxf(a.z, a.w)),
                    fmaxf(fmaxf(b.x, b.y), fmaxf(b.z, b.w)));
#pragma unroll
    for (int o = 16; o > 0; o >>= 1)
        m = fmaxf(m, __shfl_xor_sync(0xFFFFFFFFu, m, o));
    a.x = __expf(a.x - m); a.y = __expf(a.y - m); a.z = __expf(a.z - m); a.w = __expf(a.w - m);
    b.x = __expf(b.x - m); b.y = __expf(b.y - m); b.z = __expf(b.z - m); b.w = __expf(b.w - m);
    float s = a.x + a.y + a.z + a.w + b.x + b.y + b.z + b.w;
#pragma unroll
    for (int o = 16; o > 0; o >>= 1)
        s += __shfl_xor_sync(0xFFFFFFFFu, s, o);
    float inv = 1.0f / s;
    a.x *= inv; a.y *= inv; a.z *= inv; a.w *= inv;
    b.x *= inv; b.y *= inv; b.z *= inv; b.w *= inv;
    float4* op = (float4*)(out + (size_t)warp * DOUT);
    op[lane] = a;
    op[lane + 32] = b;
}

// ============================================================
// host launch
// ============================================================
extern "C" void kernel_launch(void* const* d_in, const int* in_sizes, int n_in,
                              void* d_out, int out_size)
{
    const float* x    = (const float*)d_in[0];
    const int* ei     = (const int*)d_in[1];   // int32! (JAX x64 disabled)
    const float* W1  = (const float*)d_in[2];
    const float* b1  = (const float*)d_in[3];
    const float* Wg1 = (const float*)d_in[4];
    const float* bg1 = (const float*)d_in[5];
    const float* Wg2 = (const float*)d_in[6];
    const float* bg2 = (const float*)d_in[7];
    const float* W2  = (const float*)d_in[8];
    const float* b2  = (const float*)d_in[9];
    const float* W3  = (const float*)d_in[10];
    const float* b3  = (const float*)d_in[11];
    float* out = (float*)d_out;

    int E = in_sizes[1] / 2;

    float *h, *hW, *agg;
    cudaGetSymbolAddress((void**)&h, g_h);
    cudaGetSymbolAddress((void**)&hW, g_hW);
    cudaGetSymbolAddress((void**)&agg, g_agg);

    const int ELEM4 = NN * (HH / 4);
    dim3 gemmGrid((NN + 127) / 128, HH / 128);

    // layer 1: h = relu(x @ W1 + b1), K=128
    sgemm_kernel<true, true><<<gemmGrid, 256>>>(x, W1, b1, h, NN, DIN, HH);

    // degrees (shared by both convs)
    zero_deg_kernel<<<(NN + 255) / 256, 256>>>();
    deg_count_kernel<<<(E + 255) / 256, 256>>>(ei, E);
    dinv_kernel<<<(NN + 255) / 256, 256>>>();

    // conv 1
    sgemm_kernel<false, false><<<gemmGrid, 256>>>(h, Wg1, nullptr, hW, NN, HH, HH);
    self_init_kernel<<<(ELEM4 + 255) / 256, 256>>>(hW, agg);
    scatter_kernel<<<(E * 32 + 255) / 256, 256>>>(hW, ei, agg, E);
    bias_relu_kernel<<<(ELEM4 + 255) / 256, 256>>>(agg, bg1, h);

    // conv 2
    sgemm_kernel<false, false><<<gemmGrid, 256>>>(h, Wg2, nullptr, hW, NN, HH, HH);
    self_init_kernel<<<(ELEM4 + 255) / 256, 256>>>(hW, agg);
    scatter_kernel<<<(E * 32 + 255) / 256, 256>>>(hW, ei, agg, E);
    bias_relu_kernel<<<(ELEM4 + 255) / 256, 256>>>(agg, bg2, h);

    // layer 4: hW = relu(h @ W2 + b2)
    sgemm_kernel<true, true><<<gemmGrid, 256>>>(h, W2, b2, hW, NN, HH, HH);

    // layer 5 logits: agg = hW @ W3 + b3
    sgemm_kernel<true, false><<<gemmGrid, 256>>>(hW, W3, b3, agg, NN, HH, DOUT);

    // softmax -> out
    softmax_kernel<<<(NN * 32 + 255) / 256, 256>>>(agg, out);
}